// round 13
// baseline (speedup 1.0000x reference)
#include <cuda_runtime.h>
#include <cuda_bf16.h>
#include <cstdint>

#define BB 1024
#define SS 512
#define TT 48
#define FULL 0xFFFFFFFFu
#define NPAIR 432          // warps 0..431 run two batches; 432..591 run one
#define LN2 0.69314718055994530942

typedef unsigned long long ull;

__device__ double g_scratch[BB];
__device__ unsigned int g_count = 0;
__device__ int g_len[BB];
__device__ int g_perm[BB];

__device__ __forceinline__ ull pack2f(float a, float b) {
    ull r;
    asm("mov.b64 %0, {%1, %2};" : "=l"(r) : "f"(a), "f"(b));
    return r;
}
__device__ __forceinline__ void unpack2f(ull v, float& lo, float& hi) {
    asm("mov.b64 {%0, %1}, %2;" : "=f"(lo), "=f"(hi) : "l"(v));
}
__device__ __forceinline__ void fma2(ull& acc, ull a, ull b) {
    asm("fma.rn.f32x2 %0, %1, %2, %0;" : "+l"(acc) : "l"(a), "l"(b));
}
__device__ __forceinline__ ull add2(ull a, ull b) {
    ull r;
    asm("add.rn.f32x2 %0, %1, %2;" : "=l"(r) : "l"(a), "l"(b));
    return r;
}
__device__ __forceinline__ float hsum2(ull a, ull b) {
    ull u = add2(a, b);
    float lo, hi;
    unpack2f(u, lo, hi);
    return lo + hi;
}
__device__ __forceinline__ float warp_sum_f(float v) {
    #pragma unroll
    for (int o = 16; o; o >>= 1) v += __shfl_xor_sync(FULL, v, o);
    return v;
}

// ---------- fused prepass: lengths (binary search) + counting sort ----------
extern "C" __global__ void __launch_bounds__(1024)
prep_kernel(const float* __restrict__ mask) {
    const int b = threadIdx.x;          // 1024 threads = 1024 batches
    int lo = 0, hi = SS;
    #pragma unroll
    for (int it = 0; it < 9; it++) {    // 2^9 = 512
        int mid = (lo + hi) >> 1;
        bool one = __ldg(&mask[b * SS + mid]) > 0.5f;
        lo = one ? mid : lo;
        hi = one ? hi : mid;
    }
    const int len = lo + 1;
    g_len[b] = len;

    __shared__ int cnt[SS + 1];
    __shared__ int scn[SS + 1];
    if (threadIdx.x <= SS) cnt[threadIdx.x] = 0;
    __syncthreads();
    atomicAdd(&cnt[len], 1);
    __syncthreads();
    if (threadIdx.x <= SS) scn[threadIdx.x] = cnt[threadIdx.x];
    __syncthreads();
    // Hillis-Steele inclusive scan over 513 entries
    #pragma unroll
    for (int off = 1; off <= SS; off <<= 1) {
        int v = 0;
        if (threadIdx.x <= SS && threadIdx.x >= off) v = scn[threadIdx.x - off];
        __syncthreads();
        if (threadIdx.x <= SS) scn[threadIdx.x] += v;
        __syncthreads();
    }
    if (threadIdx.x <= SS) cnt[threadIdx.x] = scn[threadIdx.x] - cnt[threadIdx.x]; // exclusive
    __syncthreads();
    int r = atomicAdd(&cnt[len], 1);
    g_perm[r] = b;                      // ascending by length
}

// One recurrence step (round-11 body). Writer-side combine: lane l and l+16
// own the same 3 columns; each sums its 24-row half, then shfl.xor(16)+add
// merges halves. Single combined p array in smem (hi half stores to shadow).
// Rescale every 4 steps by exact power-of-2 (exponent bits); esum exact int.
#define STEPX(pA_, pB_, pC_, exA_, exB_, exC_, RBOFF_, WBOFF_, DORESC_, t_) do { \
    const unsigned rb_ = pbufb + (RBOFF_);                                      \
    const unsigned wb_ = pbufb + (WBOFF_);                                      \
    float ceA_ = __expf(exA_);                                                  \
    float ceB_ = __expf(exB_);                                                  \
    float ceC_ = __expf(exC_);                                                  \
    if (DORESC_ && (((t_) & 3) == 0)) {                                         \
        float r0_;                                                              \
        asm volatile("ld.shared.f32 %0, [%1];" : "=f"(r0_) : "r"(rb_));         \
        int e_ = ((__float_as_int(r0_) >> 23) & 0xFF) - 127;                    \
        float sc_ = __int_as_float((127 - e_) << 23);                           \
        ceA_ *= sc_; ceB_ *= sc_; ceC_ *= sc_;                                  \
        esum += e_;                                                             \
    }                                                                           \
    ull a0_ = 0ull, a1_ = 0ull, b0_ = 0ull, b1_ = 0ull, c0_ = 0ull, c1_ = 0ull; \
    const unsigned lo_ = rb_ + rb4;                                             \
    _Pragma("unroll")                                                           \
    for (int c = 0; c < 3; c++) {                                               \
        ull P0, P1, P2, P3;                                                     \
        asm volatile("ld.shared.v2.u64 {%0, %1}, [%2];"                         \
            : "=l"(P0), "=l"(P1) : "r"(lo_ + c * 32));                          \
        asm volatile("ld.shared.v2.u64 {%0, %1}, [%2];"                         \
            : "=l"(P2), "=l"(P3) : "r"(lo_ + c * 32 + 16));                     \
        fma2(a0_, P0, EA[4*c  ]); fma2(b0_, P0, EB[4*c  ]); fma2(c0_, P0, EC[4*c  ]); \
        fma2(a1_, P1, EA[4*c+1]); fma2(b1_, P1, EB[4*c+1]); fma2(c1_, P1, EC[4*c+1]); \
        fma2(a0_, P2, EA[4*c+2]); fma2(b0_, P2, EB[4*c+2]); fma2(c0_, P2, EC[4*c+2]); \
        fma2(a1_, P3, EA[4*c+3]); fma2(b1_, P3, EB[4*c+3]); fma2(c1_, P3, EC[4*c+3]); \
    }                                                                           \
    float qA_ = hsum2(a0_, a1_) * ceA_;                                         \
    float qB_ = hsum2(b0_, b1_) * ceB_;                                         \
    float qC_ = hsum2(c0_, c1_) * ceC_;                                         \
    qA_ += __shfl_xor_sync(FULL, qA_, 16);                                      \
    qB_ += __shfl_xor_sync(FULL, qB_, 16);                                      \
    qC_ += __shfl_xor_sync(FULL, qC_, 16);                                      \
    pA_ = qA_; pB_ = qB_; pC_ = qC_;                                            \
    const unsigned st_ = wb_ + stoff;                                           \
    asm volatile("st.shared.f32 [%0], %1;" :: "r"(st_),       "f"(qA_));        \
    asm volatile("st.shared.f32 [%0], %1;" :: "r"(st_ + 64),  "f"(qB_));        \
    asm volatile("st.shared.f32 [%0], %1;" :: "r"(st_ + 128), "f"(qC_));        \
} while (0)

// clamped 3-column emission load for step s (branchless, always in-bounds)
#define LD3(s_, x_, y_, z_) do {                                                \
    int r_ = min((s_), len - 1);                                                \
    const float* p_ = emp + (long)r_ * TT;                                      \
    x_ = __ldg(p_ + cA); y_ = __ldg(p_ + cB); z_ = __ldg(p_ + cC);              \
} while (0)

// 148 blocks x 128 threads: 1 CTA/SM, 1 warp/SMSP. Warp k runs perm[1023-k]
// (long) then, if k < NPAIR, perm[k] (short): pair sums ~= 513 steps for all.
extern "C" __global__ void __launch_bounds__(128)
crf_kernel(const float* __restrict__ em,      // [B,S,T]
           const int*   __restrict__ tags,    // [B,S]
           const float* __restrict__ trans,   // [T,T]
           const float* __restrict__ startt,  // [T]
           const float* __restrict__ endt,    // [T]
           float* __restrict__ out)
{
    const int lane = threadIdx.x & 31;
    const int wid  = threadIdx.x >> 5;
    const int k    = blockIdx.x * 4 + wid;      // 0..591

    // [warp][parity][128 floats]: bytes 0..192 = combined p (48), 256..448 = hi shadow
    __shared__ __align__(16) float p_buf[4][2][128];

    const int j     = lane & 15;
    const int half  = lane >> 4;
    const int rbase = half * 24;
    const unsigned rb4 = (unsigned)(rbase * 4);
    const int cA = j, cB = j + 16, cC = j + 32;

    // ---- E = exp(transitions): this lane's 24 rows x 3 columns ----
    ull EA[12], EB[12], EC[12];
    #pragma unroll
    for (int kk = 0; kk < 12; kk++) {
        int r = rbase + 2 * kk;
        EA[kk] = pack2f(__expf(__ldg(&trans[r * TT + cA])),
                        __expf(__ldg(&trans[(r + 1) * TT + cA])));
        EB[kk] = pack2f(__expf(__ldg(&trans[r * TT + cB])),
                        __expf(__ldg(&trans[(r + 1) * TT + cB])));
        EC[kk] = pack2f(__expf(__ldg(&trans[r * TT + cC])),
                        __expf(__ldg(&trans[(r + 1) * TT + cC])));
    }
    const float eeA = __expf(__ldg(&endt[cA]));
    const float eeB = __expf(__ldg(&endt[cB]));
    const float eeC = __expf(__ldg(&endt[cC]));

    const unsigned pbufb = (unsigned)__cvta_generic_to_shared(&p_buf[wid][0][0]);
    const unsigned stoff = (unsigned)(half * 256 + j * 4);   // hi half -> shadow

    const int npass = (k < NPAIR) ? 2 : 1;
    #pragma unroll 1
    for (int pass = 0; pass < npass; pass++) {
        const int b   = (pass == 0) ? g_perm[BB - 1 - k] : g_perm[k];
        const int len = g_len[b];
        const float* emp = em + (long)b * SS * TT;

        // ---- gold path score ----
        float gold;
        {
            float g = 0.f;
            const long eb = (long)b * SS * TT;
            #pragma unroll 4
            for (int it = 0; it < SS / 32; it++) {
                int t = lane + it * 32;
                if (t < len) {
                    int tg = tags[b * SS + t];
                    if (t == 0) g += __ldg(&startt[tg]) + __ldg(&em[eb + tg]);
                    else {
                        int tp = tags[b * SS + t - 1];
                        g += __ldg(&trans[tg * TT + tp]) + __ldg(&em[eb + (long)t * TT + tg]);
                    }
                    if (t == len - 1) g += __ldg(&endt[tg]);
                }
            }
            gold = warp_sum_f(g);
        }

        // ---- init at t = 0: combined p on ALL lanes (both halves identical) ----
        float pA, pB, pC, sref;
        int esum = 0;
        {
            float a  = __ldg(&startt[cA]) + emp[cA];
            float bb = __ldg(&startt[cB]) + emp[cB];
            float cc = __ldg(&startt[cC]) + emp[cC];
            sref = __shfl_sync(FULL, a, 0);
            pA = __expf(a - sref);
            pB = __expf(bb - sref);
            pC = __expf(cc - sref);
            unsigned s0 = pbufb + stoff;   // parity 0 (hi half writes shadow)
            asm volatile("st.shared.f32 [%0], %1;" :: "r"(s0),       "f"(pA));
            asm volatile("st.shared.f32 [%0], %1;" :: "r"(s0 + 64),  "f"(pB));
            asm volatile("st.shared.f32 [%0], %1;" :: "r"(s0 + 128), "f"(pC));
        }

        // ---- emission register pipeline: rows t .. t+3 in e0..e3,
        //      refilled in place right after each consuming step (WAR renames) ----
        float e0A, e0B, e0C, e1A, e1B, e1C, e2A, e2B, e2C, e3A, e3B, e3C;
        LD3(1, e0A, e0B, e0C);
        LD3(2, e1A, e1B, e1C);
        LD3(3, e2A, e2B, e2C);
        LD3(4, e3A, e3B, e3C);

        int t = 1;   // stays odd at loop top -> static parities in the body
        #pragma unroll 1
        for (; t + 3 < len; t += 4) {
            STEPX(pA, pB, pC, e0A, e0B, e0C,   0u, 512u, 0, t);     LD3(t + 4, e0A, e0B, e0C);
            STEPX(pA, pB, pC, e1A, e1B, e1C, 512u,   0u, 1, t + 1); LD3(t + 5, e1A, e1B, e1C);
            STEPX(pA, pB, pC, e2A, e2B, e2C,   0u, 512u, 0, t + 2); LD3(t + 6, e2A, e2B, e2C);
            STEPX(pA, pB, pC, e3A, e3B, e3C, 512u,   0u, 1, t + 3); LD3(t + 7, e3A, e3B, e3C);
        }
        // ---- tail: up to 3 steps, parities still static (t odd here) ----
        if (t < len) { STEPX(pA, pB, pC, e0A, e0B, e0C,   0u, 512u, 0, t); t++; }
        if (t < len) { STEPX(pA, pB, pC, e1A, e1B, e1C, 512u,   0u, 1, t); t++; }
        if (t < len) { STEPX(pA, pB, pC, e2A, e2B, e2C,   0u, 512u, 0, t); t++; }

        // ---- final: fwd = sref + esum*ln2 + log(sum_c p_c * exp(end_c)) ----
        {
            float v = pA * eeA + pB * eeB + pC * eeC;
            float ssum = warp_sum_f(v) * 0.5f;   // both halves hold combined p
            if (lane == 0)
                g_scratch[b] = (double)sref + (double)esum * LN2
                             + (double)__logf(ssum) - (double)gold;
        }
    }

    // ---- fused mean: last block reduces ----
    __syncthreads();
    __shared__ bool is_last;
    if (threadIdx.x == 0) {
        __threadfence();
        unsigned r = atomicAdd(&g_count, 1u);
        is_last = (r == gridDim.x - 1);
    }
    __syncthreads();
    if (is_last) {
        __threadfence();
        double s = 0.0;
        for (int i = threadIdx.x; i < BB; i += 128) s += g_scratch[i];
        __shared__ double sh[128];
        sh[threadIdx.x] = s;
        __syncthreads();
        #pragma unroll
        for (int o = 64; o; o >>= 1) {
            if (threadIdx.x < o) sh[threadIdx.x] += sh[threadIdx.x + o];
            __syncthreads();
        }
        if (threadIdx.x == 0) {
            out[0] = (float)(sh[0] / (double)BB);
            g_count = 0;   // reset for next graph replay
        }
    }
}

extern "C" void kernel_launch(void* const* d_in, const int* in_sizes, int n_in,
                              void* d_out, int out_size) {
    const float* em     = (const float*)d_in[0];
    const int*   tags   = (const int*)d_in[1];
    const float* mask   = (const float*)d_in[2];
    const float* trans  = (const float*)d_in[3];
    const float* startt = (const float*)d_in[4];
    const float* endt   = (const float*)d_in[5];
    float* out = (float*)d_out;

    prep_kernel<<<1, 1024>>>(mask);
    crf_kernel<<<148, 128>>>(em, tags, trans, startt, endt, out);
}

// round 14
// speedup vs baseline: 1.2180x; 1.2180x over previous
#include <cuda_runtime.h>
#include <cuda_bf16.h>
#include <cstdint>

#define BB 1024
#define SS 512
#define TT 48
#define FULL 0xFFFFFFFFu
#define NPAIR 432          // warps 0..431 run two batches; 432..591 run one
#define LN2 0.69314718055994530942

typedef unsigned long long ull;

__device__ double g_scratch[BB];
__device__ unsigned int g_count = 0;
__device__ int g_len[BB];
__device__ int g_perm[BB];

__device__ __forceinline__ ull pack2f(float a, float b) {
    ull r;
    asm("mov.b64 %0, {%1, %2};" : "=l"(r) : "f"(a), "f"(b));
    return r;
}
__device__ __forceinline__ void unpack2f(ull v, float& lo, float& hi) {
    asm("mov.b64 {%0, %1}, %2;" : "=f"(lo), "=f"(hi) : "l"(v));
}
__device__ __forceinline__ void fma2(ull& acc, ull a, ull b) {
    asm("fma.rn.f32x2 %0, %1, %2, %0;" : "+l"(acc) : "l"(a), "l"(b));
}
__device__ __forceinline__ ull add2(ull a, ull b) {
    ull r;
    asm("add.rn.f32x2 %0, %1, %2;" : "=l"(r) : "l"(a), "l"(b));
    return r;
}
__device__ __forceinline__ float hsum2(ull a, ull b) {
    ull u = add2(a, b);
    float lo, hi;
    unpack2f(u, lo, hi);
    return lo + hi;
}
__device__ __forceinline__ float warp_sum_f(float v) {
    #pragma unroll
    for (int o = 16; o; o >>= 1) v += __shfl_xor_sync(FULL, v, o);
    return v;
}

// ---------- fused prepass: lengths (binary search) + counting sort ----------
extern "C" __global__ void __launch_bounds__(1024)
prep_kernel(const float* __restrict__ mask) {
    const int b = threadIdx.x;          // 1024 threads = 1024 batches
    int lo = 0, hi = SS;
    #pragma unroll
    for (int it = 0; it < 9; it++) {    // 2^9 = 512
        int mid = (lo + hi) >> 1;
        bool one = __ldg(&mask[b * SS + mid]) > 0.5f;
        lo = one ? mid : lo;
        hi = one ? hi : mid;
    }
    const int len = lo + 1;
    g_len[b] = len;

    __shared__ int cnt[SS + 1];
    __shared__ int scn[SS + 1];
    if (threadIdx.x <= SS) cnt[threadIdx.x] = 0;
    __syncthreads();
    atomicAdd(&cnt[len], 1);
    __syncthreads();
    if (threadIdx.x <= SS) scn[threadIdx.x] = cnt[threadIdx.x];
    __syncthreads();
    // Hillis-Steele inclusive scan over 513 entries
    #pragma unroll
    for (int off = 1; off <= SS; off <<= 1) {
        int v = 0;
        if (threadIdx.x <= SS && threadIdx.x >= off) v = scn[threadIdx.x - off];
        __syncthreads();
        if (threadIdx.x <= SS) scn[threadIdx.x] += v;
        __syncthreads();
    }
    if (threadIdx.x <= SS) cnt[threadIdx.x] = scn[threadIdx.x] - cnt[threadIdx.x]; // exclusive
    __syncthreads();
    int r = atomicAdd(&cnt[len], 1);
    g_perm[r] = b;                      // ascending by length
}

// One recurrence step (round-11 body, exact). Writer-side combine: lane l and
// l+16 own the same 3 columns; each sums its 24-row half, then shfl.xor(16)+add
// merges halves. Single combined p array in smem (hi half stores to shadow).
// Rescale every 4 steps by exact power-of-2 (exponent bits); esum exact int.
#define STEPX(pA_, pB_, pC_, exA_, exB_, exC_, RBOFF_, WBOFF_, DORESC_, t_) do { \
    const unsigned rb_ = pbufb + (RBOFF_);                                      \
    const unsigned wb_ = pbufb + (WBOFF_);                                      \
    float ceA_ = __expf(exA_);                                                  \
    float ceB_ = __expf(exB_);                                                  \
    float ceC_ = __expf(exC_);                                                  \
    if (DORESC_ && (((t_) & 3) == 0)) {                                         \
        float r0_;                                                              \
        asm volatile("ld.shared.f32 %0, [%1];" : "=f"(r0_) : "r"(rb_));         \
        int e_ = ((__float_as_int(r0_) >> 23) & 0xFF) - 127;                    \
        float sc_ = __int_as_float((127 - e_) << 23);                           \
        ceA_ *= sc_; ceB_ *= sc_; ceC_ *= sc_;                                  \
        esum += e_;                                                             \
    }                                                                           \
    ull a0_ = 0ull, a1_ = 0ull, b0_ = 0ull, b1_ = 0ull, c0_ = 0ull, c1_ = 0ull; \
    const unsigned lo_ = rb_ + rb4;                                             \
    _Pragma("unroll")                                                           \
    for (int c = 0; c < 3; c++) {                                               \
        ull P0, P1, P2, P3;                                                     \
        asm volatile("ld.shared.v2.u64 {%0, %1}, [%2];"                         \
            : "=l"(P0), "=l"(P1) : "r"(lo_ + c * 32));                          \
        asm volatile("ld.shared.v2.u64 {%0, %1}, [%2];"                         \
            : "=l"(P2), "=l"(P3) : "r"(lo_ + c * 32 + 16));                     \
        fma2(a0_, P0, EA[4*c  ]); fma2(b0_, P0, EB[4*c  ]); fma2(c0_, P0, EC[4*c  ]); \
        fma2(a1_, P1, EA[4*c+1]); fma2(b1_, P1, EB[4*c+1]); fma2(c1_, P1, EC[4*c+1]); \
        fma2(a0_, P2, EA[4*c+2]); fma2(b0_, P2, EB[4*c+2]); fma2(c0_, P2, EC[4*c+2]); \
        fma2(a1_, P3, EA[4*c+3]); fma2(b1_, P3, EB[4*c+3]); fma2(c1_, P3, EC[4*c+3]); \
    }                                                                           \
    float qA_ = hsum2(a0_, a1_) * ceA_;                                         \
    float qB_ = hsum2(b0_, b1_) * ceB_;                                         \
    float qC_ = hsum2(c0_, c1_) * ceC_;                                         \
    qA_ += __shfl_xor_sync(FULL, qA_, 16);                                      \
    qB_ += __shfl_xor_sync(FULL, qB_, 16);                                      \
    qC_ += __shfl_xor_sync(FULL, qC_, 16);                                      \
    pA_ = qA_; pB_ = qB_; pC_ = qC_;                                            \
    const unsigned st_ = wb_ + stoff;                                           \
    asm volatile("st.shared.f32 [%0], %1;" :: "r"(st_),       "f"(qA_));        \
    asm volatile("st.shared.f32 [%0], %1;" :: "r"(st_ + 64),  "f"(qB_));        \
    asm volatile("st.shared.f32 [%0], %1;" :: "r"(st_ + 128), "f"(qC_));        \
} while (0)

// clamped 3-column emission load for step s (branchless, always in-bounds)
#define LD3(s_, x_, y_, z_) do {                                                \
    int r_ = min((s_), len - 1);                                                \
    const float* p_ = emp + (long)r_ * TT;                                      \
    x_ = __ldg(p_ + cA); y_ = __ldg(p_ + cB); z_ = __ldg(p_ + cC);              \
} while (0)

// 148 blocks x 128 threads: 1 CTA/SM, 1 warp/SMSP. Warp k runs perm[1023-k]
// (long) then, if k < NPAIR, perm[k] (short): pair sums ~= 513 steps for all.
extern "C" __global__ void __launch_bounds__(128)
crf_kernel(const float* __restrict__ em,      // [B,S,T]
           const int*   __restrict__ tags,    // [B,S]
           const float* __restrict__ trans,   // [T,T]
           const float* __restrict__ startt,  // [T]
           const float* __restrict__ endt,    // [T]
           float* __restrict__ out)
{
    const int lane = threadIdx.x & 31;
    const int wid  = threadIdx.x >> 5;
    const int k    = blockIdx.x * 4 + wid;      // 0..591

    // [warp][parity][128 floats]: bytes 0..192 = combined p (48), 256..448 = hi shadow
    __shared__ __align__(16) float p_buf[4][2][128];

    const int j     = lane & 15;
    const int half  = lane >> 4;
    const int rbase = half * 24;
    const unsigned rb4 = (unsigned)(rbase * 4);
    const int cA = j, cB = j + 16, cC = j + 32;

    // ---- E = exp(transitions): this lane's 24 rows x 3 columns ----
    ull EA[12], EB[12], EC[12];
    #pragma unroll
    for (int kk = 0; kk < 12; kk++) {
        int r = rbase + 2 * kk;
        EA[kk] = pack2f(__expf(__ldg(&trans[r * TT + cA])),
                        __expf(__ldg(&trans[(r + 1) * TT + cA])));
        EB[kk] = pack2f(__expf(__ldg(&trans[r * TT + cB])),
                        __expf(__ldg(&trans[(r + 1) * TT + cB])));
        EC[kk] = pack2f(__expf(__ldg(&trans[r * TT + cC])),
                        __expf(__ldg(&trans[(r + 1) * TT + cC])));
    }
    const float eeA = __expf(__ldg(&endt[cA]));
    const float eeB = __expf(__ldg(&endt[cB]));
    const float eeC = __expf(__ldg(&endt[cC]));

    const unsigned pbufb = (unsigned)__cvta_generic_to_shared(&p_buf[wid][0][0]);
    const unsigned stoff = (unsigned)(half * 256 + j * 4);   // hi half -> shadow

    const int npass = (k < NPAIR) ? 2 : 1;
    #pragma unroll 1
    for (int pass = 0; pass < npass; pass++) {
        const int b   = (pass == 0) ? g_perm[BB - 1 - k] : g_perm[k];
        const int len = g_len[b];
        const float* emp = em + (long)b * SS * TT;

        // ---- gold path score ----
        float gold;
        {
            float g = 0.f;
            const long eb = (long)b * SS * TT;
            #pragma unroll 4
            for (int it = 0; it < SS / 32; it++) {
                int t = lane + it * 32;
                if (t < len) {
                    int tg = tags[b * SS + t];
                    if (t == 0) g += __ldg(&startt[tg]) + __ldg(&em[eb + tg]);
                    else {
                        int tp = tags[b * SS + t - 1];
                        g += __ldg(&trans[tg * TT + tp]) + __ldg(&em[eb + (long)t * TT + tg]);
                    }
                    if (t == len - 1) g += __ldg(&endt[tg]);
                }
            }
            gold = warp_sum_f(g);
        }

        // ---- init at t = 0: combined p on ALL lanes (both halves identical) ----
        float pA, pB, pC, sref;
        int esum = 0;
        {
            float a  = __ldg(&startt[cA]) + emp[cA];
            float bb = __ldg(&startt[cB]) + emp[cB];
            float cc = __ldg(&startt[cC]) + emp[cC];
            sref = __shfl_sync(FULL, a, 0);
            pA = __expf(a - sref);
            pB = __expf(bb - sref);
            pC = __expf(cc - sref);
            unsigned s0 = pbufb + stoff;   // parity 0 (hi half writes shadow)
            asm volatile("st.shared.f32 [%0], %1;" :: "r"(s0),       "f"(pA));
            asm volatile("st.shared.f32 [%0], %1;" :: "r"(s0 + 64),  "f"(pB));
            asm volatile("st.shared.f32 [%0], %1;" :: "r"(s0 + 128), "f"(pC));
        }

        // ---- emission register pipeline: rows t .. t+3 in e0..e3 ----
        float e0A, e0B, e0C, e1A, e1B, e1C, e2A, e2B, e2C, e3A, e3B, e3C;
        LD3(1, e0A, e0B, e0C);
        LD3(2, e1A, e1B, e1C);
        LD3(3, e2A, e2B, e2C);
        LD3(4, e3A, e3B, e3C);

        int t = 1;   // stays odd at loop top -> static parities in the body
        #pragma unroll 1
        for (; t + 3 < len; t += 4) {
            float n0A, n0B, n0C, n1A, n1B, n1C, n2A, n2B, n2C, n3A, n3B, n3C;
            LD3(t + 4, n0A, n0B, n0C);
            LD3(t + 5, n1A, n1B, n1C);
            LD3(t + 6, n2A, n2B, n2C);
            LD3(t + 7, n3A, n3B, n3C);

            STEPX(pA, pB, pC, e0A, e0B, e0C,   0u, 512u, 0, t);
            STEPX(pA, pB, pC, e1A, e1B, e1C, 512u,   0u, 1, t + 1);
            STEPX(pA, pB, pC, e2A, e2B, e2C,   0u, 512u, 0, t + 2);
            STEPX(pA, pB, pC, e3A, e3B, e3C, 512u,   0u, 1, t + 3);

            e0A = n0A; e0B = n0B; e0C = n0C;
            e1A = n1A; e1B = n1B; e1C = n1C;
            e2A = n2A; e2B = n2B; e2C = n2C;
            e3A = n3A; e3B = n3B; e3C = n3C;
        }
        // ---- tail: up to 3 steps, parities still static (t odd here) ----
        if (t < len) { STEPX(pA, pB, pC, e0A, e0B, e0C,   0u, 512u, 0, t); t++; }
        if (t < len) { STEPX(pA, pB, pC, e1A, e1B, e1C, 512u,   0u, 1, t); t++; }
        if (t < len) { STEPX(pA, pB, pC, e2A, e2B, e2C,   0u, 512u, 0, t); t++; }

        // ---- final: fwd = sref + esum*ln2 + log(sum_c p_c * exp(end_c)) ----
        {
            float v = pA * eeA + pB * eeB + pC * eeC;
            float ssum = warp_sum_f(v) * 0.5f;   // both halves hold combined p
            if (lane == 0)
                g_scratch[b] = (double)sref + (double)esum * LN2
                             + (double)__logf(ssum) - (double)gold;
        }
    }

    // ---- fused mean: last block reduces ----
    __syncthreads();
    __shared__ bool is_last;
    if (threadIdx.x == 0) {
        __threadfence();
        unsigned r = atomicAdd(&g_count, 1u);
        is_last = (r == gridDim.x - 1);
    }
    __syncthreads();
    if (is_last) {
        __threadfence();
        double s = 0.0;
        for (int i = threadIdx.x; i < BB; i += 128) s += g_scratch[i];
        __shared__ double sh[128];
        sh[threadIdx.x] = s;
        __syncthreads();
        #pragma unroll
        for (int o = 64; o; o >>= 1) {
            if (threadIdx.x < o) sh[threadIdx.x] += sh[threadIdx.x + o];
            __syncthreads();
        }
        if (threadIdx.x == 0) {
            out[0] = (float)(sh[0] / (double)BB);
            g_count = 0;   // reset for next graph replay
        }
    }
}

extern "C" void kernel_launch(void* const* d_in, const int* in_sizes, int n_in,
                              void* d_out, int out_size) {
    const float* em     = (const float*)d_in[0];
    const int*   tags   = (const int*)d_in[1];
    const float* mask   = (const float*)d_in[2];
    const float* trans  = (const float*)d_in[3];
    const float* startt = (const float*)d_in[4];
    const float* endt   = (const float*)d_in[5];
    float* out = (float*)d_out;

    prep_kernel<<<1, 1024>>>(mask);
    crf_kernel<<<148, 128>>>(em, tags, trans, startt, endt, out);
}